// round 1
// baseline (speedup 1.0000x reference)
#include <cuda_runtime.h>

// SrbQpCtrl: reference collapses to tau = 0 for every batch element.
//   Q = I, q = 0, G = -I, h = 0  =>  z* = max(0, -q/diag(Q)) = 0
//   tau = broadcast(z*) = zeros([BATCH, 10], float32)
// Input x is unused. Output is a constant 80 MB zero fill -> single memset node.

extern "C" void kernel_launch(void* const* d_in, const int* in_sizes, int n_in,
                              void* d_out, int out_size) {
    (void)d_in; (void)in_sizes; (void)n_in;
    // out_size elements of float32, all exactly 0.0f (bit pattern 0x00000000).
    cudaMemsetAsync(d_out, 0, (size_t)out_size * sizeof(float), 0);
}